// round 4
// baseline (speedup 1.0000x reference)
#include <cuda_runtime.h>
#include <cuda_bf16.h>

#define IMAGE_TOKEN_ID 31999
#define BB 4
#define LL 1024
#define DD 2048
#define NUM_VIS 576
#define NEW_LEN (LL - 1 + NUM_VIS)   // 1599
#define D4 (DD / 4)                  // 512 float4 per row
#define MERGED_ROWS (BB * NEW_LEN)   // 6396
#define MERGED_ELEMS (MERGED_ROWS * DD)
#define ROW_CTAS ((MERGED_ROWS + 1) / 2)  // 3198, 2 rows per CTA

// Route output row (b, j) with image position p to a source pointer.
// Returns nullptr for the duplicate-scatter zero row (j==0 && p!=0).
__device__ __forceinline__ const float4* route_row(
    int b, int j, int p,
    const int* __restrict__ row_ids,
    const float4* __restrict__ vis,
    const float4* __restrict__ embed)
{
    if (j >= p && j < p + NUM_VIS) {
        return vis + ((size_t)b * NUM_VIS + (j - p)) * D4;
    }
    if (j == 0 && p != 0) {
        // reference's duplicate-scatter: image row's dummy zero-write to slot 0
        // lands after text position 0's write (XLA in-order scatter).
        return nullptr;
    }
    int i = (j < p) ? j : (j - NUM_VIS + 1);
    return embed + (size_t)row_ids[i] * D4;
}

// Single fused kernel. One CTA per TWO output rows; 256 threads, 4 independent
// float4 loads per thread (front-batched for MLP). Each CTA finds its rows'
// image-token positions by scanning the L2-resident ids. Trailing blocks
// write the position_ids tail.
__global__ void __launch_bounds__(256) merge_kernel(
    const int*    __restrict__ ids,    // [B, L]
    const float4* __restrict__ vis,    // [B, NUM_VIS, D/4]
    const float4* __restrict__ embed,  // [32768, D/4]
    float4*       __restrict__ out,    // [B, NEW_LEN, D/4] (+ tail)
    int tail_n)
{
    int blk = blockIdx.x;
    int t = threadIdx.x;

    if (blk >= ROW_CTAS) {
        // position_ids tail: broadcast arange(NEW_LEN), as output dtype (fp32)
        int i = (blk - ROW_CTAS) * 256 + t;
        if (i < tail_n) {
            float* tail = (float*)out + (size_t)MERGED_ELEMS;
            tail[i] = (float)(i % NEW_LEN);
        }
        return;
    }

    int row0 = blk * 2;
    int row1 = row0 + 1;                 // MERGED_ROWS even -> always valid
    int b0 = row0 / NEW_LEN, j0 = row0 - b0 * NEW_LEN;
    int b1 = row1 / NEW_LEN, j1 = row1 - b1 * NEW_LEN;

    // ---- find image-token positions for the (1 or 2) batch rows involved ----
    __shared__ int s_p[2];
    if (t < 2) s_p[t] = 0;
    __syncthreads();
    const int* row_ids0 = ids + b0 * LL;
    #pragma unroll
    for (int k = 0; k < 4; k++) {
        int pos = t + k * 256;
        if (row_ids0[pos] == IMAGE_TOKEN_ID) atomicMax(&s_p[0], pos);
    }
    if (b1 != b0) {
        const int* row_ids1 = ids + b1 * LL;
        #pragma unroll
        for (int k = 0; k < 4; k++) {
            int pos = t + k * 256;
            if (row_ids1[pos] == IMAGE_TOKEN_ID) atomicMax(&s_p[1], pos);
        }
    }
    __syncthreads();
    int p0 = s_p[0];
    int p1 = (b1 == b0) ? p0 : s_p[1];

    // ---- route both rows ----
    const float4* s0 = route_row(b0, j0, p0, ids + b0 * LL, vis, embed);
    const float4* s1 = route_row(b1, j1, p1, ids + b1 * LL, vis, embed);

    const float4 z = make_float4(0.f, 0.f, 0.f, 0.f);
    float4 v00 = z, v01 = z, v10 = z, v11 = z;

    // 4 independent loads, front-batched for MLP
    if (s0) { v00 = __ldcs(s0 + t); v01 = __ldcs(s0 + t + 256); }
    if (s1) { v10 = __ldcs(s1 + t); v11 = __ldcs(s1 + t + 256); }

    float4* d0 = out + (size_t)row0 * D4;
    float4* d1 = out + (size_t)row1 * D4;
    d0[t]       = v00;
    d0[t + 256] = v01;
    d1[t]       = v10;
    d1[t + 256] = v11;
}

extern "C" void kernel_launch(void* const* d_in, const int* in_sizes, int n_in,
                              void* d_out, int out_size) {
    const int*    ids   = (const int*)d_in[0];            // [B, L] int32
    const float4* vis   = (const float4*)d_in[1];         // [B, NUM_VIS, D]
    const float4* embed = (const float4*)d_in[2];         // [32768, D]

    int tail_n = out_size - MERGED_ELEMS;
    if (tail_n < 0) tail_n = 0;
    int tail_blocks = (tail_n + 255) / 256;

    merge_kernel<<<ROW_CTAS + tail_blocks, 256>>>(
        ids, vis, embed, (float4*)d_out, tail_n);
}

// round 5
// speedup vs baseline: 1.0152x; 1.0152x over previous
#include <cuda_runtime.h>
#include <cuda_bf16.h>

#define IMAGE_TOKEN_ID 31999
#define BB 4
#define LL 1024
#define DD 2048
#define NUM_VIS 576
#define NEW_LEN (LL - 1 + NUM_VIS)   // 1599
#define D4 (DD / 4)                  // 512 float4 per row
#define MERGED_ROWS (BB * NEW_LEN)   // 6396
#define MERGED_ELEMS (MERGED_ROWS * DD)
#define ROWS_PER_CTA 4
#define ROW_CTAS (MERGED_ROWS / ROWS_PER_CTA)  // 1599

// Zero source row for the duplicate-scatter case (static -> zero-initialized).
__device__ float4 g_zero[D4];

// Route output row (b, j) with image position p to a source pointer.
__device__ __forceinline__ const float4* route_row(
    int b, int j, int p,
    const int* __restrict__ ids,
    const float4* __restrict__ vis,
    const float4* __restrict__ embed)
{
    if (j >= p && j < p + NUM_VIS) {
        return vis + ((size_t)b * NUM_VIS + (j - p)) * D4;
    }
    if (j == 0 && p != 0) {
        // reference's duplicate-scatter: image row's dummy zero-write to slot 0
        // lands after text position 0's write (XLA in-order scatter).
        return g_zero;
    }
    int i = (j < p) ? j : (j - NUM_VIS + 1);
    return embed + (size_t)ids[b * LL + i] * D4;
}

// Single fused kernel. One CTA per FOUR output rows; 256 threads, 8
// independent front-batched float4 loads per thread. Each CTA scans the
// L2/L1-resident ids for its (<=2) batch rows' image positions. Trailing
// blocks write the position_ids tail.
__global__ void __launch_bounds__(256) merge_kernel(
    const int*    __restrict__ ids,    // [B, L]
    const float4* __restrict__ vis,    // [B, NUM_VIS, D/4]
    const float4* __restrict__ embed,  // [32768, D/4]
    float4*       __restrict__ out,    // [B, NEW_LEN, D/4] (+ tail)
    int tail_n)
{
    int blk = blockIdx.x;
    int t = threadIdx.x;

    if (blk >= ROW_CTAS) {
        // position_ids tail: broadcast arange(NEW_LEN), as output dtype (fp32)
        int i = (blk - ROW_CTAS) * 256 + t;
        if (i < tail_n) {
            float* tail = (float*)out + (size_t)MERGED_ELEMS;
            tail[i] = (float)(i % NEW_LEN);
        }
        return;
    }

    int row0 = blk * ROWS_PER_CTA;
    int b_first = row0 / NEW_LEN;
    int b_last  = (row0 + ROWS_PER_CTA - 1) / NEW_LEN;   // <= b_first + 1

    // ---- find image-token positions for the (1 or 2) batch rows involved ----
    __shared__ int s_p[2];
    if (t < 2) s_p[t] = 0;
    __syncthreads();
    {
        const int* r0 = ids + b_first * LL;
        #pragma unroll
        for (int k = 0; k < 4; k++) {
            int pos = t + k * 256;
            if (r0[pos] == IMAGE_TOKEN_ID) atomicMax(&s_p[0], pos);
        }
        if (b_last != b_first) {
            const int* r1 = ids + b_last * LL;
            #pragma unroll
            for (int k = 0; k < 4; k++) {
                int pos = t + k * 256;
                if (r1[pos] == IMAGE_TOKEN_ID) atomicMax(&s_p[1], pos);
            }
        }
    }
    __syncthreads();
    int p0 = s_p[0];
    int p1 = s_p[1];

    // ---- route all 4 rows, then batch loads / batch stores ----
    const float4* src[ROWS_PER_CTA];
    #pragma unroll
    for (int r = 0; r < ROWS_PER_CTA; r++) {
        int row = row0 + r;
        int b = row / NEW_LEN;
        int j = row - b * NEW_LEN;
        int p = (b == b_first) ? p0 : p1;
        src[r] = route_row(b, j, p, ids, vis, embed);
    }

    float4 v[ROWS_PER_CTA][2];
    #pragma unroll
    for (int r = 0; r < ROWS_PER_CTA; r++) {
        v[r][0] = __ldcs(src[r] + t);
        v[r][1] = __ldcs(src[r] + t + 256);
    }

    float4* dst = out + (size_t)row0 * D4;
    #pragma unroll
    for (int r = 0; r < ROWS_PER_CTA; r++) {
        dst[r * D4 + t]       = v[r][0];
        dst[r * D4 + t + 256] = v[r][1];
    }
}

extern "C" void kernel_launch(void* const* d_in, const int* in_sizes, int n_in,
                              void* d_out, int out_size) {
    const int*    ids   = (const int*)d_in[0];            // [B, L] int32
    const float4* vis   = (const float4*)d_in[1];         // [B, NUM_VIS, D]
    const float4* embed = (const float4*)d_in[2];         // [32768, D]

    int tail_n = out_size - MERGED_ELEMS;
    if (tail_n < 0) tail_n = 0;
    int tail_blocks = (tail_n + 255) / 256;

    merge_kernel<<<ROW_CTAS + tail_blocks, 256>>>(
        ids, vis, embed, (float4*)d_out, tail_n);
}

// round 6
// speedup vs baseline: 1.0429x; 1.0273x over previous
#include <cuda_runtime.h>
#include <cuda_bf16.h>

#define IMAGE_TOKEN_ID 31999
#define BB 4
#define LL 1024
#define DD 2048
#define NUM_VIS 576
#define NEW_LEN (LL - 1 + NUM_VIS)   // 1599
#define D4 (DD / 4)                  // 512 float4 per row
#define MERGED_ROWS (BB * NEW_LEN)   // 6396
#define MERGED_ELEMS (MERGED_ROWS * DD)
#define ROWS_PER_CTA 4
#define ROW_CTAS (MERGED_ROWS / ROWS_PER_CTA)  // 1599

// Zero source row for the duplicate-scatter case (static -> zero-initialized).
__device__ float4 g_zero[D4];

// Route output row (b, j) with image position p to a source pointer.
__device__ __forceinline__ const float4* route_row(
    int b, int j, int p,
    const int* __restrict__ ids,
    const float4* __restrict__ vis,
    const float4* __restrict__ embed)
{
    if (j >= p && j < p + NUM_VIS) {
        return vis + ((size_t)b * NUM_VIS + (j - p)) * D4;
    }
    if (j == 0 && p != 0) {
        // reference's duplicate-scatter: image row's dummy zero-write to slot 0
        // lands after text position 0's write (XLA in-order scatter).
        return g_zero;
    }
    int i = (j < p) ? j : (j - NUM_VIS + 1);
    return embed + (size_t)ids[b * LL + i] * D4;
}

// Single fused kernel. One CTA per FOUR output rows; 256 threads, 8
// independent front-batched float4 loads per thread. Default caching policy
// everywhere: the full touched footprint (~105 MB) fits in the 126 MB L2, so
// graph-replay steady state runs mostly from L2.
__global__ void __launch_bounds__(256) merge_kernel(
    const int*    __restrict__ ids,    // [B, L]
    const float4* __restrict__ vis,    // [B, NUM_VIS, D/4]
    const float4* __restrict__ embed,  // [32768, D/4]
    float4*       __restrict__ out,    // [B, NEW_LEN, D/4] (+ tail)
    int tail_n)
{
    int blk = blockIdx.x;
    int t = threadIdx.x;

    if (blk >= ROW_CTAS) {
        // position_ids tail: broadcast arange(NEW_LEN), as output dtype (fp32)
        int i = (blk - ROW_CTAS) * 256 + t;
        if (i < tail_n) {
            float* tail = (float*)out + (size_t)MERGED_ELEMS;
            tail[i] = (float)(i % NEW_LEN);
        }
        return;
    }

    int row0 = blk * ROWS_PER_CTA;
    int b_first = row0 / NEW_LEN;
    int b_last  = (row0 + ROWS_PER_CTA - 1) / NEW_LEN;   // <= b_first + 1

    // ---- find image-token positions for the (1 or 2) batch rows involved ----
    __shared__ int s_p[2];
    if (t < 2) s_p[t] = 0;
    __syncthreads();
    {
        const int* r0 = ids + b_first * LL;
        #pragma unroll
        for (int k = 0; k < 4; k++) {
            int pos = t + k * 256;
            if (r0[pos] == IMAGE_TOKEN_ID) atomicMax(&s_p[0], pos);
        }
        if (b_last != b_first) {
            const int* r1 = ids + b_last * LL;
            #pragma unroll
            for (int k = 0; k < 4; k++) {
                int pos = t + k * 256;
                if (r1[pos] == IMAGE_TOKEN_ID) atomicMax(&s_p[1], pos);
            }
        }
    }
    __syncthreads();
    int p0 = s_p[0];
    int p1 = s_p[1];

    // ---- route all 4 rows, then batch loads / batch stores ----
    const float4* src[ROWS_PER_CTA];
    #pragma unroll
    for (int r = 0; r < ROWS_PER_CTA; r++) {
        int row = row0 + r;
        int b = row / NEW_LEN;
        int j = row - b * NEW_LEN;
        int p = (b == b_first) ? p0 : p1;
        src[r] = route_row(b, j, p, ids, vis, embed);
    }

    float4 v[ROWS_PER_CTA][2];
    #pragma unroll
    for (int r = 0; r < ROWS_PER_CTA; r++) {
        v[r][0] = src[r][t];
        v[r][1] = src[r][t + 256];
    }

    float4* dst = out + (size_t)row0 * D4;
    #pragma unroll
    for (int r = 0; r < ROWS_PER_CTA; r++) {
        dst[r * D4 + t]       = v[r][0];
        dst[r * D4 + t + 256] = v[r][1];
    }
}

extern "C" void kernel_launch(void* const* d_in, const int* in_sizes, int n_in,
                              void* d_out, int out_size) {
    const int*    ids   = (const int*)d_in[0];            // [B, L] int32
    const float4* vis   = (const float4*)d_in[1];         // [B, NUM_VIS, D]
    const float4* embed = (const float4*)d_in[2];         // [32768, D]

    int tail_n = out_size - MERGED_ELEMS;
    if (tail_n < 0) tail_n = 0;
    int tail_blocks = (tail_n + 255) / 256;

    merge_kernel<<<ROW_CTAS + tail_blocks, 256>>>(
        ids, vis, embed, (float4*)d_out, tail_n);
}